// round 16
// baseline (speedup 1.0000x reference)
#include <cuda_runtime.h>
#include <cuda_fp16.h>
#include <cstdint>

// ============================================================================
// out = LayerNorm(relu(x @ (m*W_v + (1-m)*W_r)))   [attention path is identity:
// softmax rows sum to 1 and the reference einsum contracts the softmax axis]
//   x: [131072, 256] f32,  W: [256, 512] f32,  out: [131072, 512] f32
// R16 = R15 (specialization + persistent + cross-tile prefetch + ldcs/stcs +
// 3-stage B ring at wait distance 2, KC=64) with B cp.async SPREAD ACROSS ALL
// 8 WARPS (16 cp16/thread): cuts the loader warps' per-region issue burden
// (the critical path) while costing MMA-only warps only ~128 cyc each.
// All warps commit one group per region (empty at tails) and wait<1>.
// fp16 mma.sync, 64x64 warp tiles, BM=64, NT=256.
// ============================================================================

static constexpr int K_DIM  = 256;
static constexpr int N_DIM  = 512;
static constexpr int BM     = 64;
static constexpr int KC     = 64;
static constexpr int NCH    = K_DIM / KC;   // 4
static constexpr int NTILES = 131072 / BM;  // 2048
static constexpr int NT     = 256;          // 8 warps; warp = 64 rows x 64 cols
static constexpr int GRID   = 148;

// SMEM layout (bytes)
static constexpr int SM_B  = 0;            // 3 stages x 64 KB = 192 KB
static constexpr int SM_A  = 196608;       // 2 stages x 8 KB = 16 KB
static constexpr int SM_GB = 212992;       // gamma/beta f32 = 4 KB
static constexpr int SM_PS = 217088;       // psum[64][8]+psq[64][8]+stats[64][2] = 4608
static constexpr int SMEM_TOTAL = 221696;

// Pre-swizzled fp16 B chunk images: off(n,kk) = swz(n*128 + kk*2), kk = k%64.
__device__ __align__(16) unsigned char g_Bimg[NCH][65536];

// ---------------------------------------------------------------------------
__device__ __forceinline__ uint32_t smem_u32(const void* p) {
    uint32_t r;
    asm("{ .reg .u64 t; cvta.to.shared.u64 t, %1; cvt.u32.u64 %0, t; }" : "=r"(r) : "l"(p));
    return r;
}
__host__ __device__ __forceinline__ uint32_t swz(uint32_t o) { return o ^ ((o >> 3) & 0x70); }

__device__ __forceinline__ void cp16(uint32_t d, const void* s) {
    asm volatile("cp.async.cg.shared.global [%0], [%1], 16;" :: "r"(d), "l"(s));
}
__device__ __forceinline__ void cp_commit() { asm volatile("cp.async.commit_group;"); }
template <int N>
__device__ __forceinline__ void cp_wait() { asm volatile("cp.async.wait_group %0;" :: "n"(N)); }

__device__ __forceinline__ float4 ldcs4(const float* p) {
    float4 v;
    asm volatile("ld.global.cs.v4.f32 {%0,%1,%2,%3}, [%4];"
                 : "=f"(v.x), "=f"(v.y), "=f"(v.z), "=f"(v.w) : "l"(p));
    return v;
}
__device__ __forceinline__ void stcs2(float* p, float a, float b) {
    asm volatile("st.global.cs.v2.f32 [%0], {%1,%2};" :: "l"(p), "f"(a), "f"(b) : "memory");
}

__device__ __forceinline__ void ldsm4(uint32_t* r, uint32_t a) {
    asm volatile("ldmatrix.sync.aligned.m8n8.x4.shared.b16 {%0,%1,%2,%3}, [%4];"
                 : "=r"(r[0]), "=r"(r[1]), "=r"(r[2]), "=r"(r[3]) : "r"(a));
}
__device__ __forceinline__ void hmma(float* c, const uint32_t* a, const uint32_t* b) {
    asm volatile("mma.sync.aligned.m16n8k16.row.col.f32.f16.f16.f32 "
                 "{%0,%1,%2,%3},{%4,%5,%6,%7},{%8,%9},{%0,%1,%2,%3};"
                 : "+f"(c[0]), "+f"(c[1]), "+f"(c[2]), "+f"(c[3])
                 : "r"(a[0]), "r"(a[1]), "r"(a[2]), "r"(a[3]), "r"(b[0]), "r"(b[1]));
}

// ---------------------------------------------------------------------------
// Prep: W_c = m*W_v + (1-m)*W_r -> fp16, pre-swizzled chunk images.
// ---------------------------------------------------------------------------
__global__ void prep_kernel(const float* __restrict__ Wv, const float* __restrict__ Wr,
                            const float* __restrict__ mix) {
    int gid = blockIdx.x * blockDim.x + threadIdx.x;
    if (gid >= K_DIM * N_DIM) return;
    int n = gid & 511;
    int k = gid >> 9;
    float m = 1.0f / (1.0f + expf(-mix[0]));
    float w = m * Wv[k * N_DIM + n] + (1.0f - m) * Wr[k * N_DIM + n];
    int c  = k >> 6;
    int kk = k & 63;
    uint32_t off = swz((uint32_t)(n * 128 + kk * 2));
    *(__half*)(&g_Bimg[c][off]) = __float2half(w);
}

// ---------------------------------------------------------------------------
// Persistent fused GEMM (fp16 mma.sync, hybrid-specialized) + relu + LN
// ---------------------------------------------------------------------------
__global__ void __launch_bounds__(NT, 1)
gemm_ln_kernel(const float* __restrict__ x, const float* __restrict__ gamma,
               const float* __restrict__ beta, float* __restrict__ out) {
    extern __shared__ char smem[];
    const uint32_t sb = smem_u32(smem);
    const int tid  = threadIdx.x;
    const int wn   = tid >> 5;    // warp 0..7 -> 64-col slice, all 64 rows
    const int lane = tid & 31;
    const bool loader = (wn < 4); // A-path owner: one loader warp per SMSP
    const int bid  = blockIdx.x;

    // gamma/beta into smem (once)
    {
        float* gsh = (float*)(smem + SM_GB);
        for (int i = tid; i < N_DIM; i += NT) {
            gsh[i]         = gamma[i];
            gsh[N_DIM + i] = beta[i];
        }
    }

    // ldmatrix base offsets
    const uint32_t arow = (uint32_t)((lane & 15) * 128 + (lane >> 4) * 16);
    const uint32_t brow = (uint32_t)((wn * 64 + ((lane >> 4) & 1) * 8 + (lane & 7)) * 128
                                     + ((lane >> 3) & 1) * 16);

    // Loader A indexing: 1024 float4 per chunk over 128 loader threads -> 8 each
    int arowi[8], asegi[8];
    uint32_t asoff[8];
    #pragma unroll
    for (int i = 0; i < 8; i++) {
        int idx = tid + i * 128;
        arowi[i] = idx >> 4;
        asegi[i] = (idx & 15) * 4;
        asoff[i] = swz((uint32_t)((idx >> 4) * 128 + (idx & 15) * 8));
    }

    float* psum  = (float*)(smem + SM_PS);
    float* psq   = psum + 512;
    float* stats = psq + 512;
    const float* gsh = (const float*)(smem + SM_GB);
    const float* bsh = gsh + N_DIM;

    float4 av[8];
    // ---- one-time prologue: B regions 0,1 (ALL warps, spread); A (loader) ----
    #pragma unroll
    for (int s = 0; s < 2; s++) {
        #pragma unroll
        for (int i = 0; i < 16; i++) {
            int j = tid + i * NT;          // 0..4095
            cp16(sb + SM_B + s * 65536 + j * 16, &g_Bimg[s][j * 16]);
        }
        cp_commit();
    }
    if (loader) {
        const size_t mb = (size_t)bid * BM;
        #pragma unroll
        for (int i = 0; i < 8; i++)
            av[i] = ldcs4(x + (mb + arowi[i]) * K_DIM + asegi[i]);
        #pragma unroll
        for (int i = 0; i < 8; i++) {
            __half2 h01 = __floats2half2_rn(av[i].x, av[i].y);
            __half2 h23 = __floats2half2_rn(av[i].z, av[i].w);
            *(uint2*)(smem + SM_A + asoff[i]) = make_uint2(*(uint32_t*)&h01, *(uint32_t*)&h23);
        }
        #pragma unroll
        for (int i = 0; i < 8; i++)
            av[i] = ldcs4(x + (mb + arowi[i]) * K_DIM + KC + asegi[i]);
    }

    int r = 0;   // absolute region index; B image = r & 3, B stage = r % 3
    for (int t = bid; t < NTILES; t += GRID) {
        const size_t m0 = (size_t)t * BM;
        const bool last_tile = (t + GRID >= NTILES);

        float acc[4][8][4];
        #pragma unroll
        for (int mt = 0; mt < 4; mt++)
            #pragma unroll
            for (int nt = 0; nt < 8; nt++)
                #pragma unroll
                for (int i = 0; i < 4; i++) acc[mt][nt][i] = 0.0f;

        #pragma unroll
        for (int c = 0; c < NCH; c++, r++) {
            const int stage = r % 3;
            // retire the group for THIS region (committed 2 regions ago by
            // every thread; one commit per region keeps accounting exact)
            cp_wait<1>();
            __syncthreads();               // publish stage; order chunk reuse

            // A path: loader warps only (STS next chunk, LDG chunk after)
            if (loader) {
                const bool has_nextA = !(last_tile && c == NCH - 1);
                if (has_nextA) {
                    const int nst = (c + 1) & 1;
                    #pragma unroll
                    for (int i = 0; i < 8; i++) {
                        __half2 h01 = __floats2half2_rn(av[i].x, av[i].y);
                        __half2 h23 = __floats2half2_rn(av[i].z, av[i].w);
                        *(uint2*)(smem + SM_A + nst * 8192 + asoff[i]) =
                            make_uint2(*(uint32_t*)&h01, *(uint32_t*)&h23);
                    }
                    if (c < NCH - 2) {
                        #pragma unroll
                        for (int i = 0; i < 8; i++)
                            av[i] = ldcs4(x + (m0 + arowi[i]) * K_DIM + (c + 2) * KC + asegi[i]);
                    } else if (!last_tile) {
                        const size_t mn = (size_t)(t + GRID) * BM;
                        #pragma unroll
                        for (int i = 0; i < 8; i++)
                            av[i] = ldcs4(x + (mn + arowi[i]) * K_DIM + (c - 2) * KC + asegi[i]);
                    }
                }
            }

            // B for region r+2 into stage (r+2)%3 — spread across ALL warps
            // (stage last read region r-1; ordered by this region's barrier)
            {
                const bool has_nextB = !(last_tile && c >= NCH - 2);
                if (has_nextB) {
                    const uint32_t dst = sb + SM_B + ((r + 2) % 3) * 65536;
                    const unsigned char* bimg = &g_Bimg[(r + 2) & 3][0];
                    #pragma unroll
                    for (int i = 0; i < 16; i++) {
                        int j = tid + i * NT;   // 0..4095
                        cp16(dst + j * 16, bimg + j * 16);
                    }
                }
                cp_commit();                    // every thread, every region
            }

            // ---- MMA chunk (all warps) ----
            const uint32_t Ab = sb + SM_A + (c & 1) * 8192;
            const uint32_t Bb = sb + SM_B + stage * 65536;
            uint32_t af[2][4][4];
            #pragma unroll
            for (int mt = 0; mt < 4; mt++)
                ldsm4(af[0][mt], Ab + swz(arow + mt * 2048));
            #pragma unroll
            for (int ks = 0; ks < 4; ks++) {
                const int cur = ks & 1, nxt = cur ^ 1;
                if (ks < 3)
                    #pragma unroll
                    for (int mt = 0; mt < 4; mt++)
                        ldsm4(af[nxt][mt], Ab + swz(arow + mt * 2048 + (ks + 1) * 32));
                #pragma unroll
                for (int bt = 0; bt < 4; bt++) {
                    uint32_t bh[4];
                    ldsm4(bh, Bb + swz(brow + bt * 2048 + ks * 32));
                    #pragma unroll
                    for (int mt = 0; mt < 4; mt++) {
                        hmma(acc[mt][2 * bt],     af[cur][mt], &bh[0]);
                        hmma(acc[mt][2 * bt + 1], af[cur][mt], &bh[2]);
                    }
                }
            }
        }

        // ---------------- Epilogue: relu + LayerNorm(512) ----------------
        #pragma unroll
        for (int mt = 0; mt < 4; mt++) {
            #pragma unroll
            for (int half = 0; half < 2; half++) {
                float s = 0.0f, q = 0.0f;
                #pragma unroll
                for (int nt = 0; nt < 8; nt++) {
                    float v0 = fmaxf(acc[mt][nt][half * 2 + 0], 0.0f);
                    float v1 = fmaxf(acc[mt][nt][half * 2 + 1], 0.0f);
                    s += v0 + v1;
                    q = fmaf(v0, v0, q);
                    q = fmaf(v1, v1, q);
                }
                s += __shfl_xor_sync(0xFFFFFFFFu, s, 1);
                q += __shfl_xor_sync(0xFFFFFFFFu, q, 1);
                s += __shfl_xor_sync(0xFFFFFFFFu, s, 2);
                q += __shfl_xor_sync(0xFFFFFFFFu, q, 2);
                if ((lane & 3) == 0) {
                    int rr = mt * 16 + (lane >> 2) + half * 8;
                    psum[rr * 8 + wn] = s;
                    psq[rr * 8 + wn]  = q;
                }
            }
        }
        __syncthreads();
        if (tid < BM) {
            float st = 0.0f, qt = 0.0f;
            #pragma unroll
            for (int i = 0; i < 8; i++) { st += psum[tid * 8 + i]; qt += psq[tid * 8 + i]; }
            float mean = st * (1.0f / 512.0f);
            float var  = qt * (1.0f / 512.0f) - mean * mean;
            stats[tid * 2]     = mean;
            stats[tid * 2 + 1] = rsqrtf(var + 1e-5f);
        }
        __syncthreads();

        #pragma unroll
        for (int mt = 0; mt < 4; mt++) {
            #pragma unroll
            for (int half = 0; half < 2; half++) {
                int rr = mt * 16 + (lane >> 2) + half * 8;
                float mean = stats[rr * 2];
                float rstd = stats[rr * 2 + 1];
                float* orow = out + (size_t)(m0 + rr) * N_DIM;
                #pragma unroll
                for (int nt = 0; nt < 8; nt++) {
                    int col = wn * 64 + nt * 8 + (lane & 3) * 2;
                    float ox = (fmaxf(acc[mt][nt][half * 2 + 0], 0.0f) - mean) * rstd * gsh[col]     + bsh[col];
                    float oy = (fmaxf(acc[mt][nt][half * 2 + 1], 0.0f) - mean) * rstd * gsh[col + 1] + bsh[col + 1];
                    stcs2(orow + col, ox, oy);
                }
            }
        }
        // no trailing barrier: psum/psq reuse is ordered by the next tile's
        // region-entry barriers before the next epilogue writes them
    }
}

// ---------------------------------------------------------------------------
// Host launcher. Inputs: x, W_q, W_k, W_v, W_r, mix, gamma, beta
// ---------------------------------------------------------------------------
extern "C" void kernel_launch(void* const* d_in, const int* in_sizes, int n_in,
                              void* d_out, int out_size) {
    const float* x     = (const float*)d_in[0];
    const float* Wv    = (const float*)d_in[3];
    const float* Wr    = (const float*)d_in[4];
    const float* mix   = (const float*)d_in[5];
    const float* gamma = (const float*)d_in[6];
    const float* beta  = (const float*)d_in[7];
    float* out = (float*)d_out;

    cudaFuncSetAttribute(gemm_ln_kernel, cudaFuncAttributeMaxDynamicSharedMemorySize, SMEM_TOTAL);

    prep_kernel<<<(K_DIM * N_DIM + 255) / 256, 256>>>(Wv, Wr, mix);
    gemm_ln_kernel<<<GRID, NT, SMEM_TOTAL>>>(x, gamma, beta, out);
}

// round 17
// speedup vs baseline: 1.0824x; 1.0824x over previous
#include <cuda_runtime.h>
#include <cuda_fp16.h>
#include <cstdint>

// ============================================================================
// out = LayerNorm(relu(x @ (m*W_v + (1-m)*W_r)))   [attention path is identity:
// softmax rows sum to 1 and the reference einsum contracts the softmax axis]
//   x: [131072, 256] f32,  W: [256, 512] f32,  out: [131072, 512] f32
// R17 = R15 (warp-role specialization + persistent CTAs + cross-tile prefetch
// + ldcs/stcs + 3-stage B ring at wait distance 2, KC=64) + ONE-STEP B
// FRAGMENT PIPELINE: ldmatrix for fragment (ks,bt+1) is issued before the
// HMMAs on (ks,bt), hiding the ~29-cyc LDS latency that was exposed 16x per
// warp per region. B loading stays loader-warp-only (R16's spread regressed).
// fp16 mma.sync, 64x64 warp tiles, BM=64, NT=256.
// ============================================================================

static constexpr int K_DIM  = 256;
static constexpr int N_DIM  = 512;
static constexpr int BM     = 64;
static constexpr int KC     = 64;
static constexpr int NCH    = K_DIM / KC;   // 4
static constexpr int NTILES = 131072 / BM;  // 2048
static constexpr int NT     = 256;          // 8 warps; warp = 64 rows x 64 cols
static constexpr int GRID   = 148;

// SMEM layout (bytes)
static constexpr int SM_B  = 0;            // 3 stages x 64 KB = 192 KB
static constexpr int SM_A  = 196608;       // 2 stages x 8 KB = 16 KB
static constexpr int SM_GB = 212992;       // gamma/beta f32 = 4 KB
static constexpr int SM_PS = 217088;       // psum[64][8]+psq[64][8]+stats[64][2] = 4608
static constexpr int SMEM_TOTAL = 221696;

// Pre-swizzled fp16 B chunk images: off(n,kk) = swz(n*128 + kk*2), kk = k%64.
__device__ __align__(16) unsigned char g_Bimg[NCH][65536];

// ---------------------------------------------------------------------------
__device__ __forceinline__ uint32_t smem_u32(const void* p) {
    uint32_t r;
    asm("{ .reg .u64 t; cvta.to.shared.u64 t, %1; cvt.u32.u64 %0, t; }" : "=r"(r) : "l"(p));
    return r;
}
__host__ __device__ __forceinline__ uint32_t swz(uint32_t o) { return o ^ ((o >> 3) & 0x70); }

__device__ __forceinline__ void cp16(uint32_t d, const void* s) {
    asm volatile("cp.async.cg.shared.global [%0], [%1], 16;" :: "r"(d), "l"(s));
}
__device__ __forceinline__ void cp_commit() { asm volatile("cp.async.commit_group;"); }
template <int N>
__device__ __forceinline__ void cp_wait() { asm volatile("cp.async.wait_group %0;" :: "n"(N)); }

__device__ __forceinline__ float4 ldcs4(const float* p) {
    float4 v;
    asm volatile("ld.global.cs.v4.f32 {%0,%1,%2,%3}, [%4];"
                 : "=f"(v.x), "=f"(v.y), "=f"(v.z), "=f"(v.w) : "l"(p));
    return v;
}
__device__ __forceinline__ void stcs2(float* p, float a, float b) {
    asm volatile("st.global.cs.v2.f32 [%0], {%1,%2};" :: "l"(p), "f"(a), "f"(b) : "memory");
}

__device__ __forceinline__ void ldsm4(uint32_t* r, uint32_t a) {
    asm volatile("ldmatrix.sync.aligned.m8n8.x4.shared.b16 {%0,%1,%2,%3}, [%4];"
                 : "=r"(r[0]), "=r"(r[1]), "=r"(r[2]), "=r"(r[3]) : "r"(a));
}
__device__ __forceinline__ void hmma(float* c, const uint32_t* a, const uint32_t* b) {
    asm volatile("mma.sync.aligned.m16n8k16.row.col.f32.f16.f16.f32 "
                 "{%0,%1,%2,%3},{%4,%5,%6,%7},{%8,%9},{%0,%1,%2,%3};"
                 : "+f"(c[0]), "+f"(c[1]), "+f"(c[2]), "+f"(c[3])
                 : "r"(a[0]), "r"(a[1]), "r"(a[2]), "r"(a[3]), "r"(b[0]), "r"(b[1]));
}

// ---------------------------------------------------------------------------
// Prep: W_c = m*W_v + (1-m)*W_r -> fp16, pre-swizzled chunk images.
// ---------------------------------------------------------------------------
__global__ void prep_kernel(const float* __restrict__ Wv, const float* __restrict__ Wr,
                            const float* __restrict__ mix) {
    int gid = blockIdx.x * blockDim.x + threadIdx.x;
    if (gid >= K_DIM * N_DIM) return;
    int n = gid & 511;
    int k = gid >> 9;
    float m = 1.0f / (1.0f + expf(-mix[0]));
    float w = m * Wv[k * N_DIM + n] + (1.0f - m) * Wr[k * N_DIM + n];
    int c  = k >> 6;
    int kk = k & 63;
    uint32_t off = swz((uint32_t)(n * 128 + kk * 2));
    *(__half*)(&g_Bimg[c][off]) = __float2half(w);
}

// ---------------------------------------------------------------------------
// Persistent fused GEMM (fp16 mma.sync, specialized, B-frag pipelined) + LN
// ---------------------------------------------------------------------------
__global__ void __launch_bounds__(NT, 1)
gemm_ln_kernel(const float* __restrict__ x, const float* __restrict__ gamma,
               const float* __restrict__ beta, float* __restrict__ out) {
    extern __shared__ char smem[];
    const uint32_t sb = smem_u32(smem);
    const int tid  = threadIdx.x;
    const int wn   = tid >> 5;    // warp 0..7 -> 64-col slice, all 64 rows
    const int lane = tid & 31;
    const bool loader = (wn < 4); // one loader warp per SMSP
    const int bid  = blockIdx.x;

    // gamma/beta into smem (once)
    {
        float* gsh = (float*)(smem + SM_GB);
        for (int i = tid; i < N_DIM; i += NT) {
            gsh[i]         = gamma[i];
            gsh[N_DIM + i] = beta[i];
        }
    }

    // ldmatrix base offsets
    const uint32_t arow = (uint32_t)((lane & 15) * 128 + (lane >> 4) * 16);
    const uint32_t brow = (uint32_t)((wn * 64 + ((lane >> 4) & 1) * 8 + (lane & 7)) * 128
                                     + ((lane >> 3) & 1) * 16);

    // Loader A indexing: 1024 float4 per chunk over 128 loader threads -> 8 each
    int arowi[8], asegi[8];
    uint32_t asoff[8];
    #pragma unroll
    for (int i = 0; i < 8; i++) {
        int idx = tid + i * 128;
        arowi[i] = idx >> 4;
        asegi[i] = (idx & 15) * 4;
        asoff[i] = swz((uint32_t)((idx >> 4) * 128 + (idx & 15) * 8));
    }

    float* psum  = (float*)(smem + SM_PS);
    float* psq   = psum + 512;
    float* stats = psq + 512;
    const float* gsh = (const float*)(smem + SM_GB);
    const float* bsh = gsh + N_DIM;

    float4 av[8];
    // ---- one-time prologue (loader warps): B regions 0,1; A c0 STS; c1 LDG ----
    if (loader) {
        #pragma unroll
        for (int s = 0; s < 2; s++) {
            #pragma unroll
            for (int i = 0; i < 32; i++) {
                int j = tid + i * 128;
                cp16(sb + SM_B + s * 65536 + j * 16, &g_Bimg[s][j * 16]);
            }
            cp_commit();
        }
        const size_t mb = (size_t)bid * BM;
        #pragma unroll
        for (int i = 0; i < 8; i++)
            av[i] = ldcs4(x + (mb + arowi[i]) * K_DIM + asegi[i]);
        #pragma unroll
        for (int i = 0; i < 8; i++) {
            __half2 h01 = __floats2half2_rn(av[i].x, av[i].y);
            __half2 h23 = __floats2half2_rn(av[i].z, av[i].w);
            *(uint2*)(smem + SM_A + asoff[i]) = make_uint2(*(uint32_t*)&h01, *(uint32_t*)&h23);
        }
        #pragma unroll
        for (int i = 0; i < 8; i++)
            av[i] = ldcs4(x + (mb + arowi[i]) * K_DIM + KC + asegi[i]);
    }

    int r = 0;   // absolute region index; B image = r & 3, B stage = r % 3
    for (int t = bid; t < NTILES; t += GRID) {
        const size_t m0 = (size_t)t * BM;
        const bool last_tile = (t + GRID >= NTILES);

        float acc[4][8][4];
        #pragma unroll
        for (int mt = 0; mt < 4; mt++)
            #pragma unroll
            for (int nt = 0; nt < 8; nt++)
                #pragma unroll
                for (int i = 0; i < 4; i++) acc[mt][nt][i] = 0.0f;

        #pragma unroll
        for (int c = 0; c < NCH; c++, r++) {
            const int stage = r % 3;
            // retire the group for THIS region (committed 2 regions ago);
            // one commit per region (possibly empty) keeps accounting exact
            if (loader) cp_wait<1>();
            __syncthreads();               // publish stage; order chunk reuse

            if (loader) {
                // A: STS next chunk, LDG chunk after (cross-tile at the seam)
                const bool has_nextA = !(last_tile && c == NCH - 1);
                if (has_nextA) {
                    const int nst = (c + 1) & 1;
                    #pragma unroll
                    for (int i = 0; i < 8; i++) {
                        __half2 h01 = __floats2half2_rn(av[i].x, av[i].y);
                        __half2 h23 = __floats2half2_rn(av[i].z, av[i].w);
                        *(uint2*)(smem + SM_A + nst * 8192 + asoff[i]) =
                            make_uint2(*(uint32_t*)&h01, *(uint32_t*)&h23);
                    }
                    if (c < NCH - 2) {
                        #pragma unroll
                        for (int i = 0; i < 8; i++)
                            av[i] = ldcs4(x + (m0 + arowi[i]) * K_DIM + (c + 2) * KC + asegi[i]);
                    } else if (!last_tile) {
                        const size_t mn = (size_t)(t + GRID) * BM;
                        #pragma unroll
                        for (int i = 0; i < 8; i++)
                            av[i] = ldcs4(x + (mn + arowi[i]) * K_DIM + (c - 2) * KC + asegi[i]);
                    }
                }
                // B for region r+2 into stage (r+2)%3; commit EVERY region
                const bool has_nextB = !(last_tile && c >= NCH - 2);
                if (has_nextB) {
                    const uint32_t dst = sb + SM_B + ((r + 2) % 3) * 65536;
                    const unsigned char* bimg = &g_Bimg[(r + 2) & 3][0];
                    #pragma unroll
                    for (int i = 0; i < 32; i++) {
                        int j = tid + i * 128;
                        cp16(dst + j * 16, bimg + j * 16);
                    }
                }
                cp_commit();
            }

            // ---- MMA chunk: A double-buffered AND B one-step pipelined ----
            const uint32_t Ab = sb + SM_A + (c & 1) * 8192;
            const uint32_t Bb = sb + SM_B + stage * 65536;
            uint32_t af[2][4][4];
            uint32_t bf[2][4];
            #pragma unroll
            for (int mt = 0; mt < 4; mt++)
                ldsm4(af[0][mt], Ab + swz(arow + mt * 2048));
            ldsm4(bf[0], Bb + swz(brow));          // (ks0, bt0)
            #pragma unroll
            for (int ks = 0; ks < 4; ks++) {
                const int acur = ks & 1, anxt = acur ^ 1;
                if (ks < 3)
                    #pragma unroll
                    for (int mt = 0; mt < 4; mt++)
                        ldsm4(af[anxt][mt], Ab + swz(arow + mt * 2048 + (ks + 1) * 32));
                #pragma unroll
                for (int bt = 0; bt < 4; bt++) {
                    const int bcur = (ks * 4 + bt) & 1, bnxt = bcur ^ 1;
                    // prefetch next B fragment before consuming current
                    if (bt < 3)
                        ldsm4(bf[bnxt], Bb + swz(brow + (bt + 1) * 2048 + ks * 32));
                    else if (ks < 3)
                        ldsm4(bf[bnxt], Bb + swz(brow + (ks + 1) * 32));
                    #pragma unroll
                    for (int mt = 0; mt < 4; mt++) {
                        hmma(acc[mt][2 * bt],     af[acur][mt], &bf[bcur][0]);
                        hmma(acc[mt][2 * bt + 1], af[acur][mt], &bf[bcur][2]);
                    }
                }
            }
        }

        // ---------------- Epilogue: relu + LayerNorm(512) ----------------
        #pragma unroll
        for (int mt = 0; mt < 4; mt++) {
            #pragma unroll
            for (int half = 0; half < 2; half++) {
                float s = 0.0f, q = 0.0f;
                #pragma unroll
                for (int nt = 0; nt < 8; nt++) {
                    float v0 = fmaxf(acc[mt][nt][half * 2 + 0], 0.0f);
                    float v1 = fmaxf(acc[mt][nt][half * 2 + 1], 0.0f);
                    s += v0 + v1;
                    q = fmaf(v0, v0, q);
                    q = fmaf(v1, v1, q);
                }
                s += __shfl_xor_sync(0xFFFFFFFFu, s, 1);
                q += __shfl_xor_sync(0xFFFFFFFFu, q, 1);
                s += __shfl_xor_sync(0xFFFFFFFFu, s, 2);
                q += __shfl_xor_sync(0xFFFFFFFFu, q, 2);
                if ((lane & 3) == 0) {
                    int rr = mt * 16 + (lane >> 2) + half * 8;
                    psum[rr * 8 + wn] = s;
                    psq[rr * 8 + wn]  = q;
                }
            }
        }
        __syncthreads();
        if (tid < BM) {
            float st = 0.0f, qt = 0.0f;
            #pragma unroll
            for (int i = 0; i < 8; i++) { st += psum[tid * 8 + i]; qt += psq[tid * 8 + i]; }
            float mean = st * (1.0f / 512.0f);
            float var  = qt * (1.0f / 512.0f) - mean * mean;
            stats[tid * 2]     = mean;
            stats[tid * 2 + 1] = rsqrtf(var + 1e-5f);
        }
        __syncthreads();

        #pragma unroll
        for (int mt = 0; mt < 4; mt++) {
            #pragma unroll
            for (int half = 0; half < 2; half++) {
                int rr = mt * 16 + (lane >> 2) + half * 8;
                float mean = stats[rr * 2];
                float rstd = stats[rr * 2 + 1];
                float* orow = out + (size_t)(m0 + rr) * N_DIM;
                #pragma unroll
                for (int nt = 0; nt < 8; nt++) {
                    int col = wn * 64 + nt * 8 + (lane & 3) * 2;
                    float ox = (fmaxf(acc[mt][nt][half * 2 + 0], 0.0f) - mean) * rstd * gsh[col]     + bsh[col];
                    float oy = (fmaxf(acc[mt][nt][half * 2 + 1], 0.0f) - mean) * rstd * gsh[col + 1] + bsh[col + 1];
                    stcs2(orow + col, ox, oy);
                }
            }
        }
        // no trailing barrier: psum/psq reuse is ordered by the next tile's
        // region-entry barriers before the next epilogue writes them
    }
}

// ---------------------------------------------------------------------------
// Host launcher. Inputs: x, W_q, W_k, W_v, W_r, mix, gamma, beta
// ---------------------------------------------------------------------------
extern "C" void kernel_launch(void* const* d_in, const int* in_sizes, int n_in,
                              void* d_out, int out_size) {
    const float* x     = (const float*)d_in[0];
    const float* Wv    = (const float*)d_in[3];
    const float* Wr    = (const float*)d_in[4];
    const float* mix   = (const float*)d_in[5];
    const float* gamma = (const float*)d_in[6];
    const float* beta  = (const float*)d_in[7];
    float* out = (float*)d_out;

    cudaFuncSetAttribute(gemm_ln_kernel, cudaFuncAttributeMaxDynamicSharedMemorySize, SMEM_TOTAL);

    prep_kernel<<<(K_DIM * N_DIM + 255) / 256, 256>>>(Wv, Wr, mix);
    gemm_ln_kernel<<<GRID, NT, SMEM_TOTAL>>>(x, gamma, beta, out);
}